// round 8
// baseline (speedup 1.0000x reference)
#include <cuda_runtime.h>
#include <cuda_bf16.h>
#include <cstdint>

#define B_    8
#define HW_   128
#define C_    128
#define NPIX  (B_ * HW_ * HW_)   // 131072
#define MTILE 64
#define NTILE (NPIX / MTILE)     // 2048

// Scratch
__device__ float g_v[(size_t)NPIX * C_];
__device__ float g_agg[(size_t)NPIX * C_];
// bf16-split weights, [which][k][n]
__device__ __nv_bfloat16 g_wh[2 * C_ * C_];
__device__ __nv_bfloat16 g_wl[2 * C_ * C_];

__device__ __forceinline__ uint32_t smem_u32(const void* p) {
    uint32_t a;
    asm("{ .reg .u64 t; cvta.to.shared.u64 t, %1; cvt.u32.u64 %0, t; }"
        : "=r"(a) : "l"(p));
    return a;
}

// ---------------------------------------------------------------------------
// Weight prep: Wh[k][n], Wl[k][n] = bf16 split of W[k][n]
// ---------------------------------------------------------------------------
__global__ void prep_w(const float* __restrict__ Wv, const float* __restrict__ Wp)
{
    const float* W = blockIdx.x ? Wp : Wv;
    __nv_bfloat16* oh = g_wh + blockIdx.x * C_ * C_;
    __nv_bfloat16* ol = g_wl + blockIdx.x * C_ * C_;
    for (int i = threadIdx.x; i < C_ * C_; i += blockDim.x) {
        float x = W[i];
        __nv_bfloat16 h = __float2bfloat16_rn(x);
        oh[i] = h;
        ol[i] = __float2bfloat16_rn(x - __bfloat162float(h));
    }
}

// ---------------------------------------------------------------------------
// Tensor-core GEMM (mma.sync bf16 split-x3): out[64,128] tile per CTA.
// k-outer/product-inner mainloop: Ah/Al/Bh/Bl fragments loaded ONCE per
// k-step (8 ldsm), 24 MMAs issued against them (0.333 ldsm/mma).
// 256 threads, 8 warps: (wid&1) -> 32-row block, (wid>>1) -> 32-col block.
// smem 104 KB -> 2 CTAs/SM.
// ---------------------------------------------------------------------------
#define STRIDE 136
#define SM_AH 0
#define SM_AL (SM_AH + MTILE * STRIDE * 2)       // 17408
#define SM_BH (SM_AL + MTILE * STRIDE * 2)       // 34816
#define SM_BL (SM_BH + 128 * STRIDE * 2)         // 69632
#define SM_TOTAL (SM_BL + 128 * STRIDE * 2)      // 104448

__device__ __forceinline__ void ldsm_x4(uint32_t* r, uint32_t addr) {
    asm volatile("ldmatrix.sync.aligned.m8n8.x4.shared.b16 {%0,%1,%2,%3}, [%4];"
                 : "=r"(r[0]), "=r"(r[1]), "=r"(r[2]), "=r"(r[3]) : "r"(addr));
}
__device__ __forceinline__ void ldsm_x4_t(uint32_t* r, uint32_t addr) {
    asm volatile("ldmatrix.sync.aligned.m8n8.x4.trans.shared.b16 {%0,%1,%2,%3}, [%4];"
                 : "=r"(r[0]), "=r"(r[1]), "=r"(r[2]), "=r"(r[3]) : "r"(addr));
}
__device__ __forceinline__ void mma16816(float* c, const uint32_t* a,
                                         const uint32_t* b) {
    asm volatile(
        "mma.sync.aligned.m16n8k16.row.col.f32.bf16.bf16.f32 "
        "{%0,%1,%2,%3}, {%4,%5,%6,%7}, {%8,%9}, {%0,%1,%2,%3};"
        : "+f"(c[0]), "+f"(c[1]), "+f"(c[2]), "+f"(c[3])
        : "r"(a[0]), "r"(a[1]), "r"(a[2]), "r"(a[3]), "r"(b[0]), "r"(b[1]));
}

__global__ void __launch_bounds__(256, 2)
tc_gemm(const float* __restrict__ A,
        const __nv_bfloat16* __restrict__ Wh,
        const __nv_bfloat16* __restrict__ Wl,
        const float* __restrict__ bias,
        float* __restrict__ out)
{
    extern __shared__ char smem[];
    const uint32_t sb = smem_u32(smem);
    const int tid  = threadIdx.x;
    const int lane = tid & 31;
    const int wid  = tid >> 5;
    const int wm   = wid & 1;   // 32-row block (2)
    const int wn   = wid >> 1;  // 32-col block (4)

    // ---- Fill A (64 rows, hi/lo split) ----
    const float4* Ab = (const float4*)(A + (size_t)blockIdx.x * MTILE * C_);
    #pragma unroll
    for (int it = 0; it < 8; it++) {
        const int i = tid + it * 256;       // 0..2047
        const int row = i >> 5, c4 = i & 31;
        float4 a = Ab[i];
        __nv_bfloat16 h0 = __float2bfloat16_rn(a.x);
        __nv_bfloat16 h1 = __float2bfloat16_rn(a.y);
        __nv_bfloat16 h2 = __float2bfloat16_rn(a.z);
        __nv_bfloat16 h3 = __float2bfloat16_rn(a.w);
        __nv_bfloat16 l0 = __float2bfloat16_rn(a.x - __bfloat162float(h0));
        __nv_bfloat16 l1 = __float2bfloat16_rn(a.y - __bfloat162float(h1));
        __nv_bfloat16 l2 = __float2bfloat16_rn(a.z - __bfloat162float(h2));
        __nv_bfloat16 l3 = __float2bfloat16_rn(a.w - __bfloat162float(h3));
        uint64_t hv = (uint64_t)__bfloat16_as_ushort(h0)
                    | ((uint64_t)__bfloat16_as_ushort(h1) << 16)
                    | ((uint64_t)__bfloat16_as_ushort(h2) << 32)
                    | ((uint64_t)__bfloat16_as_ushort(h3) << 48);
        uint64_t lv = (uint64_t)__bfloat16_as_ushort(l0)
                    | ((uint64_t)__bfloat16_as_ushort(l1) << 16)
                    | ((uint64_t)__bfloat16_as_ushort(l2) << 32)
                    | ((uint64_t)__bfloat16_as_ushort(l3) << 48);
        const uint32_t off = row * (STRIDE * 2) + c4 * 8;
        *(uint64_t*)(smem + SM_AH + off) = hv;
        *(uint64_t*)(smem + SM_AL + off) = lv;
    }
    // ---- Fill B (128 rows, pre-split [k][n]) ----
    const uint4* bh4 = (const uint4*)Wh;
    const uint4* bl4 = (const uint4*)Wl;
    #pragma unroll
    for (int it = 0; it < 8; it++) {
        const int i = tid + it * 256;       // 0..2047
        const int row = i >> 4, c8 = i & 15;
        const uint32_t off = row * (STRIDE * 2) + c8 * 16;
        *(uint4*)(smem + SM_BH + off) = bh4[i];
        *(uint4*)(smem + SM_BL + off) = bl4[i];
    }
    __syncthreads();

    // ---- Mainloop: k-outer, 3 products inner sharing fragments ----
    float acc[2][4][4];
    #pragma unroll
    for (int h = 0; h < 2; h++)
        #pragma unroll
        for (int j = 0; j < 4; j++)
            #pragma unroll
            for (int e = 0; e < 4; e++) acc[h][j][e] = 0.f;

    const int arow = wm * 32 + (lane & 15);
    const int acol_off = (lane >> 4) * 8;
    const int brow = (lane & 15);
    const int bcol = wn * 32 + (lane >> 4) * 8;

    #pragma unroll
    for (int k0 = 0; k0 < 128; k0 += 16) {
        uint32_t ah[2][4], al[2][4], bh[8], bl[8];
        const uint32_t aoff0 = (arow * STRIDE + k0 + acol_off) * 2;
        const uint32_t aoff1 = ((arow + 16) * STRIDE + k0 + acol_off) * 2;
        ldsm_x4(ah[0], sb + SM_AH + aoff0);
        ldsm_x4(ah[1], sb + SM_AH + aoff1);
        ldsm_x4(al[0], sb + SM_AL + aoff0);
        ldsm_x4(al[1], sb + SM_AL + aoff1);
        const uint32_t boff0 = ((k0 + brow) * STRIDE + bcol) * 2;
        const uint32_t boff1 = ((k0 + brow) * STRIDE + bcol + 16) * 2;
        ldsm_x4_t(bh + 0, sb + SM_BH + boff0);
        ldsm_x4_t(bh + 4, sb + SM_BH + boff1);
        ldsm_x4_t(bl + 0, sb + SM_BL + boff0);
        ldsm_x4_t(bl + 4, sb + SM_BL + boff1);

        #pragma unroll
        for (int h = 0; h < 2; h++) {
            // product 0: Ah@Bh
            mma16816(acc[h][0], ah[h], bh + 0);
            mma16816(acc[h][1], ah[h], bh + 2);
            mma16816(acc[h][2], ah[h], bh + 4);
            mma16816(acc[h][3], ah[h], bh + 6);
            // product 1: Ah@Bl
            mma16816(acc[h][0], ah[h], bl + 0);
            mma16816(acc[h][1], ah[h], bl + 2);
            mma16816(acc[h][2], ah[h], bl + 4);
            mma16816(acc[h][3], ah[h], bl + 6);
            // product 2: Al@Bh
            mma16816(acc[h][0], al[h], bh + 0);
            mma16816(acc[h][1], al[h], bh + 2);
            mma16816(acc[h][2], al[h], bh + 4);
            mma16816(acc[h][3], al[h], bh + 6);
        }
    }

    // ---- Epilogue ----
    const int r0 = wm * 32 + (lane >> 2);
    const int cb = wn * 32 + (lane & 3) * 2;
    float* ob = out + (size_t)blockIdx.x * MTILE * C_;
    #pragma unroll
    for (int j = 0; j < 4; j++) {
        const int col = cb + j * 8;
        const float2 bias2 = *(const float2*)(bias + col);
        #pragma unroll
        for (int h = 0; h < 2; h++) {
            float* p0 = ob + (size_t)(r0 + h * 16) * C_ + col;
            float* p1 = ob + (size_t)(r0 + h * 16 + 8) * C_ + col;
            *(float2*)p0 = make_float2(acc[h][j][0] + bias2.x,
                                       acc[h][j][1] + bias2.y);
            *(float2*)p1 = make_float2(acc[h][j][2] + bias2.x,
                                       acc[h][j][3] + bias2.y);
        }
    }
}

// ---------------------------------------------------------------------------
// Superpixel-gated 7x7 neighborhood aggregation. Warp per pixel (~38us).
// ---------------------------------------------------------------------------
__global__ void __launch_bounds__(256) agg_kernel(const float* __restrict__ v,
                                                  const float* __restrict__ attn,
                                                  const int*   __restrict__ sp,
                                                  float* __restrict__ out)
{
    const int lane = threadIdx.x & 31;
    const int wid  = threadIdx.x >> 5;
    const int pix  = blockIdx.x * 8 + wid;
    const int x = pix & 127;
    const int y = (pix >> 7) & 127;
    const int b = pix >> 14;

    const int*   spb = sp + (b << 14);
    const float* vb  = v + (((size_t)b << 14) * C_);
    const int spc = spb[(y << 7) | x];

    int si = y - 3; si = si < 0 ? 0 : (si > HW_ - 7 ? HW_ - 7 : si);
    int sj = x - 3; sj = sj < 0 ? 0 : (sj > HW_ - 7 ? HW_ - 7 : sj);
    const int base_np = si * HW_ + sj;

    int k1 = lane;
    int ki1 = (k1 * 37) >> 8;
    unsigned m0 = __ballot_sync(0xffffffffu,
                                spb[base_np + ki1 * HW_ + (k1 - ki1 * 7)] == spc);
    int k2 = lane + 32; int k2c = k2 > 48 ? 48 : k2;
    int ki2 = (k2c * 37) >> 8;
    unsigned m1 = __ballot_sync(0xffffffffu,
        (k2 < 49) && (spb[base_np + ki2 * HW_ + (k2c - ki2 * 7)] == spc));

    const float* ab = attn +
        ((((size_t)(b * 4 + (lane >> 3)) * HW_ + y) * HW_ + x)) * 49;

    float4 acc = make_float4(0.f, 0.f, 0.f, 0.f);
    while (m0) {
        int k = __ffs(m0) - 1; m0 &= m0 - 1;
        int ki = (k * 37) >> 8;
        int np = base_np + ki * HW_ + (k - ki * 7);
        float a = __ldg(ab + k);
        float4 vv = *(const float4*)(vb + (size_t)np * C_ + lane * 4);
        acc.x += a * vv.x; acc.y += a * vv.y;
        acc.z += a * vv.z; acc.w += a * vv.w;
    }
    while (m1) {
        int k = (__ffs(m1) - 1) + 32; m1 &= m1 - 1;
        int ki = (k * 37) >> 8;
        int np = base_np + ki * HW_ + (k - ki * 7);
        float a = __ldg(ab + k);
        float4 vv = *(const float4*)(vb + (size_t)np * C_ + lane * 4);
        acc.x += a * vv.x; acc.y += a * vv.y;
        acc.z += a * vv.z; acc.w += a * vv.w;
    }
    *(float4*)(out + (size_t)pix * C_ + lane * 4) = acc;
}

// ---------------------------------------------------------------------------
// Launch
// ---------------------------------------------------------------------------
extern "C" void kernel_launch(void* const* d_in, const int* in_sizes, int n_in,
                              void* d_out, int out_size)
{
    const float* x    = (const float*)d_in[0];
    const float* attn = (const float*)d_in[1];
    const int*   sp   = (const int*)  d_in[2];
    const float* Wv   = (const float*)d_in[3];
    const float* bv   = (const float*)d_in[4];
    const float* Wp   = (const float*)d_in[5];
    const float* bp   = (const float*)d_in[6];
    float*       out  = (float*)d_out;

    float* vbuf = nullptr;
    float* aggbuf = nullptr;
    __nv_bfloat16* wh = nullptr;
    __nv_bfloat16* wl = nullptr;
    cudaGetSymbolAddress((void**)&vbuf, g_v);
    cudaGetSymbolAddress((void**)&aggbuf, g_agg);
    cudaGetSymbolAddress((void**)&wh, g_wh);
    cudaGetSymbolAddress((void**)&wl, g_wl);

    cudaFuncSetAttribute(tc_gemm, cudaFuncAttributeMaxDynamicSharedMemorySize,
                         SM_TOTAL);

    prep_w<<<2, 256>>>(Wv, Wp);
    tc_gemm<<<NTILE, 256, SM_TOTAL>>>(x, wh, wl, bv, vbuf);
    agg_kernel<<<NPIX / 8, 256>>>(vbuf, attn, sp, aggbuf);
    tc_gemm<<<NTILE, 256, SM_TOTAL>>>(aggbuf, wh + C_ * C_,
                                      wl + C_ * C_, bp, out);
}

// round 9
// speedup vs baseline: 1.1378x; 1.1378x over previous
#include <cuda_runtime.h>
#include <cuda_bf16.h>
#include <cstdint>

#define B_    8
#define HW_   128
#define C_    128
#define NPIX  (B_ * HW_ * HW_)   // 131072
#define MTILE 64
#define NTILE (NPIX / MTILE)     // 2048

// Scratch
__device__ float g_v[(size_t)NPIX * C_];
__device__ __nv_bfloat16 g_aggh[(size_t)NPIX * C_];
__device__ __nv_bfloat16 g_aggl[(size_t)NPIX * C_];
// bf16-split weights, [which][k][n]
__device__ __nv_bfloat16 g_wh[2 * C_ * C_];
__device__ __nv_bfloat16 g_wl[2 * C_ * C_];

__device__ __forceinline__ uint32_t smem_u32(const void* p) {
    uint32_t a;
    asm("{ .reg .u64 t; cvta.to.shared.u64 t, %1; cvt.u32.u64 %0, t; }"
        : "=r"(a) : "l"(p));
    return a;
}
__device__ __forceinline__ void cp_async16(uint32_t dst, const void* src) {
    asm volatile("cp.async.cg.shared.global [%0], [%1], 16;"
                 :: "r"(dst), "l"(src) : "memory");
}
__device__ __forceinline__ void cp_async_wait_all() {
    asm volatile("cp.async.commit_group;" ::: "memory");
    asm volatile("cp.async.wait_group 0;" ::: "memory");
}

// ---------------------------------------------------------------------------
// Weight prep: Wh[k][n], Wl[k][n] = bf16 split of W[k][n]
// ---------------------------------------------------------------------------
__global__ void prep_w(const float* __restrict__ Wv, const float* __restrict__ Wp)
{
    const float* W = blockIdx.x ? Wp : Wv;
    __nv_bfloat16* oh = g_wh + blockIdx.x * C_ * C_;
    __nv_bfloat16* ol = g_wl + blockIdx.x * C_ * C_;
    for (int i = threadIdx.x; i < C_ * C_; i += blockDim.x) {
        float x = W[i];
        __nv_bfloat16 h = __float2bfloat16_rn(x);
        oh[i] = h;
        ol[i] = __float2bfloat16_rn(x - __bfloat162float(h));
    }
}

// ---------------------------------------------------------------------------
// Shared GEMM pieces
// ---------------------------------------------------------------------------
#define STRIDE 136
#define SM_AH 0
#define SM_AL (SM_AH + MTILE * STRIDE * 2)       // 17408
#define SM_BH (SM_AL + MTILE * STRIDE * 2)       // 34816
#define SM_BL (SM_BH + 128 * STRIDE * 2)         // 69632
#define SM_TOTAL (SM_BL + 128 * STRIDE * 2)      // 104448

__device__ __forceinline__ void ldsm_x4(uint32_t* r, uint32_t addr) {
    asm volatile("ldmatrix.sync.aligned.m8n8.x4.shared.b16 {%0,%1,%2,%3}, [%4];"
                 : "=r"(r[0]), "=r"(r[1]), "=r"(r[2]), "=r"(r[3]) : "r"(addr));
}
__device__ __forceinline__ void ldsm_x4_t(uint32_t* r, uint32_t addr) {
    asm volatile("ldmatrix.sync.aligned.m8n8.x4.trans.shared.b16 {%0,%1,%2,%3}, [%4];"
                 : "=r"(r[0]), "=r"(r[1]), "=r"(r[2]), "=r"(r[3]) : "r"(addr));
}
__device__ __forceinline__ void mma16816(float* c, const uint32_t* a,
                                         const uint32_t* b) {
    asm volatile(
        "mma.sync.aligned.m16n8k16.row.col.f32.bf16.bf16.f32 "
        "{%0,%1,%2,%3}, {%4,%5,%6,%7}, {%8,%9}, {%0,%1,%2,%3};"
        : "+f"(c[0]), "+f"(c[1]), "+f"(c[2]), "+f"(c[3])
        : "r"(a[0]), "r"(a[1]), "r"(a[2]), "r"(a[3]), "r"(b[0]), "r"(b[1]));
}

// mainloop + epilogue shared by both gemm variants
__device__ __forceinline__ void gemm_core(uint32_t sb, int lane, int wm, int wn,
                                          const float* bias, float* ob)
{
    float acc[2][4][4];
    #pragma unroll
    for (int h = 0; h < 2; h++)
        #pragma unroll
        for (int j = 0; j < 4; j++)
            #pragma unroll
            for (int e = 0; e < 4; e++) acc[h][j][e] = 0.f;

    const int arow = wm * 32 + (lane & 15);
    const int acol_off = (lane >> 4) * 8;
    const int brow = (lane & 15);
    const int bcol = wn * 32 + (lane >> 4) * 8;

    #pragma unroll
    for (int k0 = 0; k0 < 128; k0 += 16) {
        uint32_t ah[2][4], al[2][4], bh[8], bl[8];
        const uint32_t aoff0 = (arow * STRIDE + k0 + acol_off) * 2;
        const uint32_t aoff1 = ((arow + 16) * STRIDE + k0 + acol_off) * 2;
        ldsm_x4(ah[0], sb + SM_AH + aoff0);
        ldsm_x4(ah[1], sb + SM_AH + aoff1);
        ldsm_x4(al[0], sb + SM_AL + aoff0);
        ldsm_x4(al[1], sb + SM_AL + aoff1);
        const uint32_t boff0 = ((k0 + brow) * STRIDE + bcol) * 2;
        const uint32_t boff1 = ((k0 + brow) * STRIDE + bcol + 16) * 2;
        ldsm_x4_t(bh + 0, sb + SM_BH + boff0);
        ldsm_x4_t(bh + 4, sb + SM_BH + boff1);
        ldsm_x4_t(bl + 0, sb + SM_BL + boff0);
        ldsm_x4_t(bl + 4, sb + SM_BL + boff1);

        #pragma unroll
        for (int h = 0; h < 2; h++) {
            mma16816(acc[h][0], ah[h], bh + 0);
            mma16816(acc[h][1], ah[h], bh + 2);
            mma16816(acc[h][2], ah[h], bh + 4);
            mma16816(acc[h][3], ah[h], bh + 6);
            mma16816(acc[h][0], ah[h], bl + 0);
            mma16816(acc[h][1], ah[h], bl + 2);
            mma16816(acc[h][2], ah[h], bl + 4);
            mma16816(acc[h][3], ah[h], bl + 6);
            mma16816(acc[h][0], al[h], bh + 0);
            mma16816(acc[h][1], al[h], bh + 2);
            mma16816(acc[h][2], al[h], bh + 4);
            mma16816(acc[h][3], al[h], bh + 6);
        }
    }

    const int r0 = wm * 32 + (lane >> 2);
    const int cb = wn * 32 + (lane & 3) * 2;
    #pragma unroll
    for (int j = 0; j < 4; j++) {
        const int col = cb + j * 8;
        const float2 bias2 = *(const float2*)(bias + col);
        #pragma unroll
        for (int h = 0; h < 2; h++) {
            float* p0 = ob + (size_t)(r0 + h * 16) * C_ + col;
            float* p1 = ob + (size_t)(r0 + h * 16 + 8) * C_ + col;
            *(float2*)p0 = make_float2(acc[h][j][0] + bias2.x,
                                       acc[h][j][1] + bias2.y);
            *(float2*)p1 = make_float2(acc[h][j][2] + bias2.x,
                                       acc[h][j][3] + bias2.y);
        }
    }
}

// ---------------------------------------------------------------------------
// GEMM1: fp32 A input (converted in-kernel), B via cp.async.
// ---------------------------------------------------------------------------
__global__ void __launch_bounds__(256, 2)
tc_gemm_f32(const float* __restrict__ A,
            const __nv_bfloat16* __restrict__ Wh,
            const __nv_bfloat16* __restrict__ Wl,
            const float* __restrict__ bias,
            float* __restrict__ out)
{
    extern __shared__ char smem[];
    const uint32_t sb = smem_u32(smem);
    const int tid  = threadIdx.x;
    const int lane = tid & 31;
    const int wid  = tid >> 5;

    // B via cp.async (L2-hot)
    #pragma unroll
    for (int it = 0; it < 8; it++) {
        const int i = tid + it * 256;       // 0..2047
        const int row = i >> 4, c = i & 15;
        const uint32_t doff = row * (STRIDE * 2) + c * 16;
        cp_async16(sb + SM_BH + doff, (const char*)Wh + row * 256 + c * 16);
        cp_async16(sb + SM_BL + doff, (const char*)Wl + row * 256 + c * 16);
    }

    // A: LDG fp32 + split + STS
    const float4* Ab = (const float4*)(A + (size_t)blockIdx.x * MTILE * C_);
    #pragma unroll
    for (int it = 0; it < 8; it++) {
        const int i = tid + it * 256;       // 0..2047
        const int row = i >> 5, c4 = i & 31;
        float4 a = Ab[i];
        __nv_bfloat16 h0 = __float2bfloat16_rn(a.x);
        __nv_bfloat16 h1 = __float2bfloat16_rn(a.y);
        __nv_bfloat16 h2 = __float2bfloat16_rn(a.z);
        __nv_bfloat16 h3 = __float2bfloat16_rn(a.w);
        __nv_bfloat16 l0 = __float2bfloat16_rn(a.x - __bfloat162float(h0));
        __nv_bfloat16 l1 = __float2bfloat16_rn(a.y - __bfloat162float(h1));
        __nv_bfloat16 l2 = __float2bfloat16_rn(a.z - __bfloat162float(h2));
        __nv_bfloat16 l3 = __float2bfloat16_rn(a.w - __bfloat162float(h3));
        uint64_t hv = (uint64_t)__bfloat16_as_ushort(h0)
                    | ((uint64_t)__bfloat16_as_ushort(h1) << 16)
                    | ((uint64_t)__bfloat16_as_ushort(h2) << 32)
                    | ((uint64_t)__bfloat16_as_ushort(h3) << 48);
        uint64_t lv = (uint64_t)__bfloat16_as_ushort(l0)
                    | ((uint64_t)__bfloat16_as_ushort(l1) << 16)
                    | ((uint64_t)__bfloat16_as_ushort(l2) << 32)
                    | ((uint64_t)__bfloat16_as_ushort(l3) << 48);
        const uint32_t off = row * (STRIDE * 2) + c4 * 8;
        *(uint64_t*)(smem + SM_AH + off) = hv;
        *(uint64_t*)(smem + SM_AL + off) = lv;
    }
    cp_async_wait_all();
    __syncthreads();

    gemm_core(sb, lane, wid & 1, wid >> 1, bias,
              out + (size_t)blockIdx.x * MTILE * C_);
}

// ---------------------------------------------------------------------------
// GEMM2: pre-split bf16 A input (from agg), everything via cp.async.
// ---------------------------------------------------------------------------
__global__ void __launch_bounds__(256, 2)
tc_gemm_bf(const __nv_bfloat16* __restrict__ Ah,
           const __nv_bfloat16* __restrict__ Al,
           const __nv_bfloat16* __restrict__ Wh,
           const __nv_bfloat16* __restrict__ Wl,
           const float* __restrict__ bias,
           float* __restrict__ out)
{
    extern __shared__ char smem[];
    const uint32_t sb = smem_u32(smem);
    const int tid  = threadIdx.x;
    const int lane = tid & 31;
    const int wid  = tid >> 5;

    // A via cp.async (DRAM): 64 rows x 256B per split
    const char* ahb = (const char*)(Ah + (size_t)blockIdx.x * MTILE * C_);
    const char* alb = (const char*)(Al + (size_t)blockIdx.x * MTILE * C_);
    #pragma unroll
    for (int it = 0; it < 4; it++) {
        const int i = tid + it * 256;       // 0..1023
        const int row = i >> 4, c = i & 15;
        const uint32_t doff = row * (STRIDE * 2) + c * 16;
        const int soff = row * 256 + c * 16;
        cp_async16(sb + SM_AH + doff, ahb + soff);
        cp_async16(sb + SM_AL + doff, alb + soff);
    }
    // B via cp.async (L2-hot): 128 rows x 256B per split
    #pragma unroll
    for (int it = 0; it < 8; it++) {
        const int i = tid + it * 256;       // 0..2047
        const int row = i >> 4, c = i & 15;
        const uint32_t doff = row * (STRIDE * 2) + c * 16;
        const int soff = row * 256 + c * 16;
        cp_async16(sb + SM_BH + doff, (const char*)Wh + soff);
        cp_async16(sb + SM_BL + doff, (const char*)Wl + soff);
    }
    cp_async_wait_all();
    __syncthreads();

    gemm_core(sb, lane, wid & 1, wid >> 1, bias,
              out + (size_t)blockIdx.x * MTILE * C_);
}

// ---------------------------------------------------------------------------
// Superpixel-gated 7x7 neighborhood aggregation. Warp per pixel.
// Output written as bf16 hi/lo split (feeds gemm2 directly).
// ---------------------------------------------------------------------------
__global__ void __launch_bounds__(256) agg_kernel(const float* __restrict__ v,
                                                  const float* __restrict__ attn,
                                                  const int*   __restrict__ sp,
                                                  __nv_bfloat16* __restrict__ outh,
                                                  __nv_bfloat16* __restrict__ outl)
{
    const int lane = threadIdx.x & 31;
    const int wid  = threadIdx.x >> 5;
    const int pix  = blockIdx.x * 8 + wid;
    const int x = pix & 127;
    const int y = (pix >> 7) & 127;
    const int b = pix >> 14;

    const int*   spb = sp + (b << 14);
    const float* vb  = v + (((size_t)b << 14) * C_);
    const int spc = spb[(y << 7) | x];

    int si = y - 3; si = si < 0 ? 0 : (si > HW_ - 7 ? HW_ - 7 : si);
    int sj = x - 3; sj = sj < 0 ? 0 : (sj > HW_ - 7 ? HW_ - 7 : sj);
    const int base_np = si * HW_ + sj;

    int k1 = lane;
    int ki1 = (k1 * 37) >> 8;
    unsigned m0 = __ballot_sync(0xffffffffu,
                                spb[base_np + ki1 * HW_ + (k1 - ki1 * 7)] == spc);
    int k2 = lane + 32; int k2c = k2 > 48 ? 48 : k2;
    int ki2 = (k2c * 37) >> 8;
    unsigned m1 = __ballot_sync(0xffffffffu,
        (k2 < 49) && (spb[base_np + ki2 * HW_ + (k2c - ki2 * 7)] == spc));

    const float* ab = attn +
        ((((size_t)(b * 4 + (lane >> 3)) * HW_ + y) * HW_ + x)) * 49;

    float4 acc = make_float4(0.f, 0.f, 0.f, 0.f);
    while (m0) {
        int k = __ffs(m0) - 1; m0 &= m0 - 1;
        int ki = (k * 37) >> 8;
        int np = base_np + ki * HW_ + (k - ki * 7);
        float a = __ldg(ab + k);
        float4 vv = *(const float4*)(vb + (size_t)np * C_ + lane * 4);
        acc.x += a * vv.x; acc.y += a * vv.y;
        acc.z += a * vv.z; acc.w += a * vv.w;
    }
    while (m1) {
        int k = (__ffs(m1) - 1) + 32; m1 &= m1 - 1;
        int ki = (k * 37) >> 8;
        int np = base_np + ki * HW_ + (k - ki * 7);
        float a = __ldg(ab + k);
        float4 vv = *(const float4*)(vb + (size_t)np * C_ + lane * 4);
        acc.x += a * vv.x; acc.y += a * vv.y;
        acc.z += a * vv.z; acc.w += a * vv.w;
    }

    // split write: hi/lo bf16
    __nv_bfloat16 h0 = __float2bfloat16_rn(acc.x);
    __nv_bfloat16 h1 = __float2bfloat16_rn(acc.y);
    __nv_bfloat16 h2 = __float2bfloat16_rn(acc.z);
    __nv_bfloat16 h3 = __float2bfloat16_rn(acc.w);
    __nv_bfloat16 l0 = __float2bfloat16_rn(acc.x - __bfloat162float(h0));
    __nv_bfloat16 l1 = __float2bfloat16_rn(acc.y - __bfloat162float(h1));
    __nv_bfloat16 l2 = __float2bfloat16_rn(acc.z - __bfloat162float(h2));
    __nv_bfloat16 l3 = __float2bfloat16_rn(acc.w - __bfloat162float(h3));
    uint2 hv, lv;
    hv.x = (uint32_t)__bfloat16_as_ushort(h0) | ((uint32_t)__bfloat16_as_ushort(h1) << 16);
    hv.y = (uint32_t)__bfloat16_as_ushort(h2) | ((uint32_t)__bfloat16_as_ushort(h3) << 16);
    lv.x = (uint32_t)__bfloat16_as_ushort(l0) | ((uint32_t)__bfloat16_as_ushort(l1) << 16);
    lv.y = (uint32_t)__bfloat16_as_ushort(l2) | ((uint32_t)__bfloat16_as_ushort(l3) << 16);
    *(uint2*)(outh + (size_t)pix * C_ + lane * 4) = hv;
    *(uint2*)(outl + (size_t)pix * C_ + lane * 4) = lv;
}

// ---------------------------------------------------------------------------
// Launch
// ---------------------------------------------------------------------------
extern "C" void kernel_launch(void* const* d_in, const int* in_sizes, int n_in,
                              void* d_out, int out_size)
{
    const float* x    = (const float*)d_in[0];
    const float* attn = (const float*)d_in[1];
    const int*   sp   = (const int*)  d_in[2];
    const float* Wv   = (const float*)d_in[3];
    const float* bv   = (const float*)d_in[4];
    const float* Wp   = (const float*)d_in[5];
    const float* bp   = (const float*)d_in[6];
    float*       out  = (float*)d_out;

    float* vbuf = nullptr;
    __nv_bfloat16 *aggh = nullptr, *aggl = nullptr, *wh = nullptr, *wl = nullptr;
    cudaGetSymbolAddress((void**)&vbuf, g_v);
    cudaGetSymbolAddress((void**)&aggh, g_aggh);
    cudaGetSymbolAddress((void**)&aggl, g_aggl);
    cudaGetSymbolAddress((void**)&wh, g_wh);
    cudaGetSymbolAddress((void**)&wl, g_wl);

    cudaFuncSetAttribute(tc_gemm_f32, cudaFuncAttributeMaxDynamicSharedMemorySize, SM_TOTAL);
    cudaFuncSetAttribute(tc_gemm_bf, cudaFuncAttributeMaxDynamicSharedMemorySize, SM_TOTAL);

    prep_w<<<2, 256>>>(Wv, Wp);
    tc_gemm_f32<<<NTILE, 256, SM_TOTAL>>>(x, wh, wl, bv, vbuf);
    agg_kernel<<<NPIX / 8, 256>>>(vbuf, attn, sp, aggh, aggl);
    tc_gemm_bf<<<NTILE, 256, SM_TOTAL>>>(aggh, aggl, wh + C_ * C_,
                                         wl + C_ * C_, bp, out);
}